// round 6
// baseline (speedup 1.0000x reference)
#include <cuda_runtime.h>
#include <cstdint>

#define NBINS   36
#define HIDDEN  128
#define THREADS 128
#define ITILE   8       // agents per block  -> grid = 1024 blocks (tail ~1%)
#define LANES   16      // j-lanes per agent (16 unique jt addrs per warp -> 2 wf LDS.128)
#define JCHUNK  512     // j per staged chunk

// One fused kernel: block = 8 agents x ALL j. Per-thread private SMEM hist
// (layout [bin][tid] -> bank tid%32, conflict-free). No global scratch,
// no atomics; 36->128 linear fused as epilogue.
__global__ __launch_bounds__(THREADS, 8)
void occ_fused_kernel(const float2* __restrict__ obs,
                      const float*  __restrict__ W,
                      const float*  __restrict__ bias,
                      float* __restrict__ out, int N) {
    __shared__ int hist[NBINS * THREADS];                          // 18 KB
    __shared__ __align__(16) unsigned long long jt[2][JCHUNK];     // 8 KB

    const int tid  = threadIdx.x;
    const int lane = tid & (LANES - 1);
    const int il   = tid >> 4;                 // agent slot 0..7
    const int i0   = blockIdx.x * ITILE;
    const int i    = i0 + il;

    float2 pi = (i < N) ? obs[i] : make_float2(0.f, 0.f);
    const bool ivalid = (i < N) && (pi.x == pi.x) && (pi.y == pi.y);
    float nx = ivalid ? -pi.x : -1e38f;        // invalid i -> r huge-negative -> rejected
    float ny = ivalid ? -pi.y : -1e38f;

    unsigned long long nxi, two2, three3;
    asm("mov.b64 %0, {%1, %2};" : "=l"(nxi)    : "f"(nx),   "f"(ny));
    asm("mov.b64 %0, {%1, %2};" : "=l"(two2)   : "f"(2.0f), "f"(2.0f));
    asm("mov.b64 %0, {%1, %2};" : "=l"(three3) : "f"(3.0f), "f"(3.0f));

    #pragma unroll
    for (int k = 0; k < NBINS; k++) hist[k * THREADS + tid] = 0;

    const int nchunk = (N + JCHUNK - 1) / JCHUNK;

    // Stage one chunk: 4 points (32B) per thread. NaN/OOB j -> +3e38 (rejected;
    // asymmetric vs -1e38 on i so invalid+invalid pairs stay invalid).
    auto stage = [&](int c, int bufb) {
        int j = c * JCHUNK + tid * 4;
        float4 v0, v1;
        if (j + 3 < N) {
            v0 = *(const float4*)(&obs[j]);
            v1 = *(const float4*)(&obs[j + 2]);
        } else {
            float2 t;
            t = (j     < N) ? obs[j]     : make_float2(3e38f, 3e38f); v0.x = t.x; v0.y = t.y;
            t = (j + 1 < N) ? obs[j + 1] : make_float2(3e38f, 3e38f); v0.z = t.x; v0.w = t.y;
            t = (j + 2 < N) ? obs[j + 2] : make_float2(3e38f, 3e38f); v1.x = t.x; v1.y = t.y;
            t = (j + 3 < N) ? obs[j + 3] : make_float2(3e38f, 3e38f); v1.z = t.x; v1.w = t.y;
        }
        if (!(v0.x == v0.x) || !(v0.y == v0.y)) { v0.x = 3e38f; v0.y = 3e38f; }
        if (!(v0.z == v0.z) || !(v0.w == v0.w)) { v0.z = 3e38f; v0.w = 3e38f; }
        if (!(v1.x == v1.x) || !(v1.y == v1.y)) { v1.x = 3e38f; v1.y = 3e38f; }
        if (!(v1.z == v1.z) || !(v1.w == v1.w)) { v1.z = 3e38f; v1.w = 3e38f; }
        unsigned long long p0, p1, p2, p3;
        asm("mov.b64 %0, {%1, %2};" : "=l"(p0) : "f"(v0.x), "f"(v0.y));
        asm("mov.b64 %0, {%1, %2};" : "=l"(p1) : "f"(v0.z), "f"(v0.w));
        asm("mov.b64 %0, {%1, %2};" : "=l"(p2) : "f"(v1.x), "f"(v1.y));
        asm("mov.b64 %0, {%1, %2};" : "=l"(p3) : "f"(v1.z), "f"(v1.w));
        *(ulonglong2*)&jt[bufb][4 * tid]     = make_ulonglong2(p0, p1);
        *(ulonglong2*)&jt[bufb][4 * tid + 2] = make_ulonglong2(p2, p3);
    };

    int* const hrow = hist + tid;

    // Per point: d = RN(p - pi); r = RN(2d + 3)  [bit-exact vs reference];
    // floor via FADD.RZ magic: bits(rz(r + 2^23)) = 0x4B000000 + floor(r), r >= 0.
    // Negative / inf / huge r all fail the unsigned < 6 checks.
#define PROC_PT(P) do {                                                         \
        unsigned long long d_, r_;                                             \
        asm("add.rn.f32x2 %0, %1, %2;" : "=l"(d_) : "l"(P), "l"(nxi));         \
        asm("fma.rn.f32x2 %0, %1, %2, %3;"                                     \
            : "=l"(r_) : "l"(d_), "l"(two2), "l"(three3));                     \
        float rx_, ry_;                                                        \
        asm("mov.b64 {%0, %1}, %2;" : "=f"(rx_), "=f"(ry_) : "l"(r_));         \
        int tx_ = __float_as_int(__fadd_rz(rx_, 8388608.0f)) - 0x4B000000;     \
        int ty_ = __float_as_int(__fadd_rz(ry_, 8388608.0f)) - 0x4B000000;     \
        if ((unsigned)tx_ < 6u && (unsigned)ty_ < 6u)                          \
            hrow[(tx_ * 6 + ty_) * THREADS]++;                                 \
    } while (0)

    int buf = 0;
    stage(0, 0);
    __syncthreads();
    for (int c = 0; c < nchunk; c++) {
        if (c + 1 < nchunk) stage(c + 1, buf ^ 1);
        const unsigned long long* jb = jt[buf];
        // Interleaved lane assignment: lane l, iter u -> point pair u*16 + l.
        // LDS.128: 16 unique 16B addrs per warp (il duplicates broadcast) -> 2 wf.
        #pragma unroll 4
        for (int u = 0; u < JCHUNK / (2 * LANES); u++) {
            ulonglong2 e = *(const ulonglong2*)&jb[2 * (u * LANES + lane)];
            PROC_PT(e.x);
            PROC_PT(e.y);
        }
        __syncthreads();
        buf ^= 1;
    }
#undef PROC_PT

    // Remove self-pair: lands exactly at r=(3,3) -> bin 21, counted by the lane
    // that owns point j==i within its chunk.
    if (tid < ITILE) {
        int ii = i0 + tid;
        if (ii < N) {
            float2 p = obs[ii];
            if (p.x == p.x && p.y == p.y) {
                int ln = ((ii & (JCHUNK - 1)) >> 1) & (LANES - 1);
                hist[21 * THREADS + tid * LANES + ln] -= 1;
            }
        }
    }
    __syncthreads();

    // Reduce 16 lane-hists per agent -> occ_s[8][36] (reuses jt storage).
    float* occ_s = (float*)jt;
    for (int idx = tid; idx < ITILE * NBINS; idx += THREADS) {
        int iL = idx / NBINS, b = idx - iL * NBINS;
        const int* hp = hist + b * THREADS + iL * LANES;
        int s = 0;
        #pragma unroll
        for (int l = 0; l < LANES; l++) s += hp[l];
        occ_s[idx] = (float)s;
    }
    __syncthreads();

    // Fused linear: out[i][h] = b[h] + sum_k occ[i][k] * W[h][k].
    // THREADS == HIDDEN: tid is the output channel; 8 agents per thread.
    {
        const int h = tid;
        float w[NBINS];
        #pragma unroll
        for (int k = 0; k < NBINS; k++) w[k] = W[h * NBINS + k];
        const float bh = bias[h];
        #pragma unroll
        for (int r = 0; r < ITILE; r++) {
            int ii = i0 + r;
            if (ii >= N) break;
            float acc = bh;
            #pragma unroll
            for (int k = 0; k < NBINS; k++)
                acc = fmaf(occ_s[r * NBINS + k], w[k], acc);
            out[ii * HIDDEN + h] = acc;
        }
    }
}

extern "C" void kernel_launch(void* const* d_in, const int* in_sizes, int n_in,
                              void* d_out, int out_size) {
    const float2* obs  = (const float2*)d_in[0];
    const float*  W    = (const float*)d_in[1];
    const float*  bias = (const float*)d_in[2];
    float* out = (float*)d_out;
    const int N = in_sizes[0] / 2;

    int nb = (N + ITILE - 1) / ITILE;
    occ_fused_kernel<<<nb, THREADS>>>(obs, W, bias, out, N);
}